// round 16
// baseline (speedup 1.0000x reference)
#include <cuda_runtime.h>
#include <cuda_fp16.h>
#include <math.h>
#include <stdint.h>

#define BB   8
#define TOK  327680

// ---------------- scratch ----------------
__device__ float g_t  [(size_t)TOK * 48];
__device__ float g_cat[(size_t)TOK * 96];
__device__ uint32_t g_wts[115200];   // pre-permuted tf32 weights

// weight offsets (words)
#define OFF_QKV0  0
#define OFF_QKV1  6912
#define OFF_PROJ0 13824
#define OFF_PROJ1 16128
#define OFF_FF1_0 18432
#define OFF_FF1_1 27648
#define OFF_FF2_0 36864
#define OFF_FF2_1 46080
#define OFF_PW1   55296
#define OFF_PW2   92160
#define OFF_SC    110592

__device__ __forceinline__ float gelu_exact(float v) {
    return 0.5f * v * (1.0f + erff(v * 0.70710678118654752f));
}
__device__ __forceinline__ uint32_t f2tf(float f) {
    uint32_t u;
    asm("cvt.rna.tf32.f32 %0, %1;" : "=r"(u) : "f"(f));
    return u;
}
__device__ __forceinline__ int PERM(int kk) { return 4 * (kk & 3) + (kk >> 2); }

#define MMA_TF32(c, a0, a1, a2, a3, b0, b1)                                 \
    asm volatile("mma.sync.aligned.m16n8k8.row.col.f32.tf32.tf32.f32 "     \
                 "{%0,%1,%2,%3}, {%4,%5,%6,%7}, {%8,%9}, {%0,%1,%2,%3};\n" \
                 : "+f"(c[0]), "+f"(c[1]), "+f"(c[2]), "+f"(c[3])          \
                 : "r"(a0), "r"(a1), "r"(a2), "r"(a3), "r"(b0), "r"(b1))

__device__ __forceinline__ uint4 ldw4(const uint32_t* __restrict__ Wt, int K,
                                      int c, int s, int m4) {
    return *(const uint4*)&Wt[(size_t)c * K + s * 16 + 4 * m4];
}

// ---------------- ONE fused weight prep kernel ----------------
__global__ void __launch_bounds__(256) k_prep_all(const float* __restrict__ qkv_w,
                                                  const float* __restrict__ proj_w,
                                                  const float* __restrict__ ff1_w,
                                                  const float* __restrict__ ff2_w,
                                                  const float* __restrict__ pw1_w,
                                                  const float* __restrict__ pw2_w,
                                                  const float* __restrict__ sc_w,
                                                  uint32_t* __restrict__ wt) {
    int b = blockIdx.x;
    if (b >= 432) {   // sc_w[o][c] (48x96): Wt[o][c-permuted]
        int i = (b - 432) * 256 + threadIdx.x;
        if (i < 48 * 96) {
            int o = i / 96, k = i % 96;
            int kk = k & 15;
            int pk = (k & ~15) + 4 * (kk & 3) + (kk >> 2);
            wt[OFF_SC + (size_t)o * 96 + pk] = f2tf(sc_w[i]);
        }
        return;
    }
    const float* W;
    uint32_t* Wt;
    int K, N, base;
    if (b < 27)       { W = qkv_w;          Wt = wt + OFF_QKV0;  K = 48;  N = 144; base = b; }
    else if (b < 54)  { W = qkv_w + 6912;   Wt = wt + OFF_QKV1;  K = 48;  N = 144; base = b - 27; }
    else if (b < 63)  { W = proj_w;         Wt = wt + OFF_PROJ0; K = 48;  N = 48;  base = b - 54; }
    else if (b < 72)  { W = proj_w + 2304;  Wt = wt + OFF_PROJ1; K = 48;  N = 48;  base = b - 63; }
    else if (b < 108) { W = ff1_w;          Wt = wt + OFF_FF1_0; K = 48;  N = 192; base = b - 72; }
    else if (b < 144) { W = ff1_w + 9216;   Wt = wt + OFF_FF1_1; K = 48;  N = 192; base = b - 108; }
    else if (b < 180) { W = ff2_w;          Wt = wt + OFF_FF2_0; K = 192; N = 48;  base = b - 144; }
    else if (b < 216) { W = ff2_w + 9216;   Wt = wt + OFF_FF2_1; K = 192; N = 48;  base = b - 180; }
    else if (b < 360) { W = pw1_w;          Wt = wt + OFF_PW1;   K = 96;  N = 384; base = b - 216; }
    else              { W = pw2_w;          Wt = wt + OFF_PW2;   K = 384; N = 48;  base = b - 360; }
    int i = base * 256 + threadIdx.x;
    if (i < K * N) {
        int k = i / N, c = i % N;
        int kk = k & 15;
        int pk = (k & ~15) + 4 * (kk & 3) + (kk >> 2);
        Wt[(size_t)c * K + pk] = f2tf(W[i]);
    }
}

// =====================================================================
// F1: fused qkv GEMM + banded attention + proj GEMM + residual
// =====================================================================
__global__ void __launch_bounds__(192, 3) f1_layer(const uint32_t* __restrict__ wq,
                                                   const float* __restrict__ qkv_b,
                                                   const uint32_t* __restrict__ wp,
                                                   const float* __restrict__ proj_b) {
    __shared__ uint32_t sAs[3 * 1600];
    __shared__ __half  sQKV[80 * 144];
    const int tid = threadIdx.x, lane = tid & 31, warp = tid >> 5;
    const int m4 = lane & 3, g8 = lane >> 2;
    const size_t row0 = (size_t)blockIdx.x * 80;

#pragma unroll
    for (int i = tid; i < 960; i += 192) {
        int row = i / 12, k0 = (i % 12) * 4;
        float4 v = *(const float4*)&g_t[(row0 + row) * 48 + k0];
        uint32_t* d = &sAs[(k0 >> 4) * 1600 + row * 20 + ((k0 & 15) >> 2)];
        d[0] = f2tf(v.x); d[4] = f2tf(v.y); d[8] = f2tf(v.z); d[12] = f2tf(v.w);
    }
    __syncthreads();

    {
        const int C = warp * 24;
        float acc[5][3][4] = {};
#pragma unroll
        for (int s = 0; s < 3; s++) {
            uint4 bf[3];
#pragma unroll
            for (int n = 0; n < 3; n++)
                bf[n] = ldw4(wq, 48, C + n * 8 + g8, s, m4);
#pragma unroll
            for (int a = 0; a < 5; a++) {
                int r = a * 16 + g8;
                uint4 af0 = *(const uint4*)&sAs[s * 1600 + r * 20 + m4 * 4];
                uint4 af1 = *(const uint4*)&sAs[s * 1600 + (r + 8) * 20 + m4 * 4];
#pragma unroll
                for (int n = 0; n < 3; n++) {
                    MMA_TF32(acc[a][n], af0.x, af1.x, af0.y, af1.y, bf[n].x, bf[n].y);
                    MMA_TF32(acc[a][n], af0.z, af1.z, af0.w, af1.w, bf[n].z, bf[n].w);
                }
            }
        }
#pragma unroll
        for (int a = 0; a < 5; a++) {
            int r = a * 16 + g8;
#pragma unroll
            for (int n = 0; n < 3; n++) {
                int c = C + n * 8 + 2 * m4;
                float b0 = qkv_b[c], b1 = qkv_b[c + 1];
                sQKV[r * 144 + c]           = __float2half(acc[a][n][0] + b0);
                sQKV[r * 144 + c + 1]       = __float2half(acc[a][n][1] + b1);
                sQKV[(r + 8) * 144 + c]     = __float2half(acc[a][n][2] + b0);
                sQKV[(r + 8) * 144 + c + 1] = __float2half(acc[a][n][3] + b1);
            }
        }
    }
    __syncthreads();

    {
        const int pair = tid & 63, chunk = tid >> 6;
        const int sl = pair >> 3, hh = pair & 7;
        const int ibeg = (chunk == 0) ? 0 : (chunk == 1) ? 4 : 7;
        const int iend = (chunk == 0) ? 4 : (chunk == 1) ? 7 : 10;
        const __half* base = sQKV + sl * 1440;
        const float scale = 0.40824829046386301637f;
        for (int i = ibeg; i < iend; i++) {
            const __half* ki = base + i * 144 + 48 + hh * 6;
            int jlo = (i > 0) ? i - 1 : 0;
            int jhi = (i < 9) ? i + 1 : 9;
            float lg[3];
            float mx = -1e30f;
            for (int j = jlo; j <= jhi; j++) {
                const __half* qj = base + j * 144 + hh * 6;
                float d = 0.f;
#pragma unroll
                for (int dd = 0; dd < 6; dd++)
                    d += __half2float(ki[dd]) * __half2float(qj[dd]);
                d *= scale;
                lg[j - jlo] = d;
                mx = fmaxf(mx, d);
            }
            float se = 0.f;
            for (int j = jlo; j <= jhi; j++) {
                lg[j - jlo] = expf(lg[j - jlo] - mx);
                se += lg[j - jlo];
            }
            float inv = 1.f / se;
            int row = sl * 10 + i;
#pragma unroll
            for (int dd = 0; dd < 6; dd++) {
                float o = 0.f;
                for (int j = jlo; j <= jhi; j++)
                    o += lg[j - jlo] * __half2float(base[j * 144 + 96 + hh * 6 + dd]);
                o *= inv;
                int col = hh * 6 + dd;
                sAs[(col >> 4) * 1600 + row * 20 + PERM(col & 15)] = f2tf(o);
            }
        }
    }
    __syncthreads();

    {
        const int C = warp * 8;
        float acc[5][4] = {};
#pragma unroll
        for (int s = 0; s < 3; s++) {
            uint4 bf = ldw4(wp, 48, C + g8, s, m4);
#pragma unroll
            for (int a = 0; a < 5; a++) {
                int r = a * 16 + g8;
                uint4 af0 = *(const uint4*)&sAs[s * 1600 + r * 20 + m4 * 4];
                uint4 af1 = *(const uint4*)&sAs[s * 1600 + (r + 8) * 20 + m4 * 4];
                MMA_TF32(acc[a], af0.x, af1.x, af0.y, af1.y, bf.x, bf.y);
                MMA_TF32(acc[a], af0.z, af1.z, af0.w, af1.w, bf.z, bf.w);
            }
        }
        const int c = C + 2 * m4;
        const float b0 = proj_b[c], b1 = proj_b[c + 1];
#pragma unroll
        for (int a = 0; a < 5; a++) {
            int r = a * 16 + g8;
            float2 t0 = *(const float2*)&g_t[(row0 + r) * 48 + c];
            float2 t1 = *(const float2*)&g_t[(row0 + r + 8) * 48 + c];
            *(float2*)&g_t[(row0 + r) * 48 + c] =
                make_float2(acc[a][0] + b0 + t0.x, acc[a][1] + b1 + t0.y);
            *(float2*)&g_t[(row0 + r + 8) * 48 + c] =
                make_float2(acc[a][2] + b0 + t1.x, acc[a][3] + b1 + t1.y);
        }
    }
}

// =====================================================================
// F2: fused ff1+GELU -> ff2 + residual. 32 rows, 128 threads.
// GEMM1 split into two 96-col halves; GEMM2 partially accumulated per half.
// smem 23.5KB, regs capped for 6 blocks/SM.
// =====================================================================
template<bool CAT>
__global__ void __launch_bounds__(128, 6) f2_ff(const uint32_t* __restrict__ w1,
                                                const float* __restrict__ b1,
                                                const uint32_t* __restrict__ w2,
                                                const float* __restrict__ b2) {
    __shared__ uint32_t sA[3 * 640];     // 3 slabs x 32 x 20
    __shared__ uint32_t sH[6 * 640];     // 6 slabs (96 hidden cols per half)
    const int tid = threadIdx.x, lane = tid & 31, warp = tid >> 5;
    const int m4 = lane & 3, g8 = lane >> 2;
    const size_t row0 = (size_t)blockIdx.x * 32;

#pragma unroll
    for (int i = tid; i < 384; i += 128) {
        int row = i / 12, k0 = (i % 12) * 4;
        float4 v = *(const float4*)&g_t[(row0 + row) * 48 + k0];
        uint32_t* d = &sA[(k0 >> 4) * 640 + row * 20 + ((k0 & 15) >> 2)];
        d[0] = f2tf(v.x); d[4] = f2tf(v.y); d[8] = f2tf(v.z); d[12] = f2tf(v.w);
    }
    __syncthreads();

    const int R2 = (warp >> 1) * 16, C2 = (warp & 1) * 24;
    float acc2[3][4] = {};

#pragma unroll 1
    for (int half = 0; half < 2; half++) {
        // GEMM1 half: 32 x 96, K=48; warp covers 32 rows x 24 cols
        {
            const int Cg = half * 96 + warp * 24;   // global hidden col base
            float acc[2][3][4] = {};
#pragma unroll
            for (int s = 0; s < 3; s++) {
                uint4 af[2][2];
#pragma unroll
                for (int m = 0; m < 2; m++) {
                    int r = m * 16 + g8;
                    af[m][0] = *(const uint4*)&sA[s * 640 + r * 20 + m4 * 4];
                    af[m][1] = *(const uint4*)&sA[s * 640 + (r + 8) * 20 + m4 * 4];
                }
                uint4 bf[3];
#pragma unroll
                for (int n = 0; n < 3; n++)
                    bf[n] = ldw4(w1, 48, Cg + n * 8 + g8, s, m4);
#pragma unroll
                for (int m = 0; m < 2; m++)
#pragma unroll
                    for (int n = 0; n < 3; n++) {
                        MMA_TF32(acc[m][n], af[m][0].x, af[m][1].x, af[m][0].y, af[m][1].y, bf[n].x, bf[n].y);
                        MMA_TF32(acc[m][n], af[m][0].z, af[m][1].z, af[m][0].w, af[m][1].w, bf[n].z, bf[n].w);
                    }
            }
#pragma unroll
            for (int m = 0; m < 2; m++) {
                int r = m * 16 + g8;
#pragma unroll
                for (int n = 0; n < 3; n++) {
                    int cl = warp * 24 + n * 8 + 2 * m4;   // local col in half
                    int cg = half * 96 + cl;
                    float bb0 = b1[cg], bb1 = b1[cg + 1];
                    int s0 = (cl >> 4) * 640, p0 = PERM(cl & 15);
                    int s1 = ((cl + 1) >> 4) * 640, p1 = PERM((cl + 1) & 15);
                    sH[s0 + r * 20 + p0]       = f2tf(gelu_exact(acc[m][n][0] + bb0));
                    sH[s1 + r * 20 + p1]       = f2tf(gelu_exact(acc[m][n][1] + bb1));
                    sH[s0 + (r + 8) * 20 + p0] = f2tf(gelu_exact(acc[m][n][2] + bb0));
                    sH[s1 + (r + 8) * 20 + p1] = f2tf(gelu_exact(acc[m][n][3] + bb1));
                }
            }
        }
        __syncthreads();
        // GEMM2 partial: 32x48, K-slab = this half's 96
        {
#pragma unroll
            for (int s = 0; s < 6; s++) {
                int r = R2 + g8;
                uint4 af0 = *(const uint4*)&sH[s * 640 + r * 20 + m4 * 4];
                uint4 af1 = *(const uint4*)&sH[s * 640 + (r + 8) * 20 + m4 * 4];
#pragma unroll
                for (int n = 0; n < 3; n++) {
                    uint4 bf = ldw4(w2, 192, C2 + n * 8 + g8, half * 6 + s, m4);
                    MMA_TF32(acc2[n], af0.x, af1.x, af0.y, af1.y, bf.x, bf.y);
                    MMA_TF32(acc2[n], af0.z, af1.z, af0.w, af1.w, bf.z, bf.w);
                }
            }
        }
        __syncthreads();
    }

    // epilogue
    {
        const int r = R2 + g8;
        const size_t rowA = row0 + r, rowB = row0 + r + 8;
        size_t pixA = 0, pixB = 0;
        if (CAT) {
            int bA = (int)(rowA / 40960), remA = (int)(rowA % 40960);
            int bB = (int)(rowB / 40960), remB = (int)(rowB % 40960);
            pixA = ((size_t)(bA * 10 + remA % 10) * 4096 + remA / 10) * 96 + 48;
            pixB = ((size_t)(bB * 10 + remB % 10) * 4096 + remB / 10) * 96 + 48;
        }
#pragma unroll
        for (int n = 0; n < 3; n++) {
            int c = C2 + n * 8 + 2 * m4;
            float bb0 = b2[c], bb1 = b2[c + 1];
            float2 t0 = *(const float2*)&g_t[rowA * 48 + c];
            float2 t1 = *(const float2*)&g_t[rowB * 48 + c];
            float2 v0 = make_float2(acc2[n][0] + bb0 + t0.x, acc2[n][1] + bb1 + t0.y);
            float2 v1 = make_float2(acc2[n][2] + bb0 + t1.x, acc2[n][3] + bb1 + t1.y);
            if (CAT) {
                *(float2*)&g_cat[pixA + c] = v0;
                *(float2*)&g_cat[pixB + c] = v1;
            } else {
                *(float2*)&g_t[rowA * 48 + c] = v0;
                *(float2*)&g_t[rowB * 48 + c] = v1;
            }
        }
    }
}

// =====================================================================
// F3v2: dwconv+LN + sc GEMM + pw1+GELU + pw2, one block per image row.
// =====================================================================
__global__ void __launch_bounds__(256, 2) f3_tail(const uint32_t* __restrict__ w1,
                                                  const float* __restrict__ pw1_b,
                                                  const uint32_t* __restrict__ w2,
                                                  const float* __restrict__ pw2_b,
                                                  const uint32_t* __restrict__ wsc,
                                                  const float* __restrict__ sc_b,
                                                  const float* __restrict__ wdw,
                                                  const float* __restrict__ bdw,
                                                  const float* __restrict__ gam,
                                                  const float* __restrict__ bet,
                                                  float* __restrict__ out) {
    extern __shared__ uint32_t dyn[];
    uint32_t* sA   = dyn;                    // 7680 words
    float*    srow = (float*)(dyn + 7680);   // 18432 floats
    uint32_t* sH   = dyn + 7680;             // 15360 words (aliases srow)
    float*    sOut = (float*)dyn;            // 3136 floats (aliases sA)
    __shared__ float sw[864], sb[96], sg[96], sbe[96];

    const int tid = threadIdx.x, lane = tid & 31, warp = tid >> 5;
    const int m4 = lane & 3, g8 = lane >> 2;
    const int n_img = blockIdx.x >> 6, h = blockIdx.x & 63;
    const int hw0 = h * 64;

    for (int i = tid; i < 864; i += 256) sw[i] = wdw[i];
    if (tid < 96) {
        sb[tid] = bdw[tid];
        sg[tid] = gam[tid];
        sbe[tid] = bet[tid];
    }

#pragma unroll
    for (int i = tid; i < 3 * 1536; i += 256) {
        int j = i / 1536, off = (i % 1536) * 4;
        int hh = h + j - 1;
        float4 v = make_float4(0.f, 0.f, 0.f, 0.f);
        if (hh >= 0 && hh < 64)
            v = *(const float4*)&g_cat[((size_t)n_img * 4096 + hh * 64) * 96 + off];
        *(float4*)&srow[j * 6144 + off] = v;
    }
    __syncthreads();

    for (int i = tid; i < 6144; i += 256) {
        int w = i / 96, c = i % 96;
        sA[(c >> 4) * 1280 + w * 20 + PERM(c & 15)] = f2tf(srow[6144 + w * 96 + c]);
    }
    __syncthreads();

    const int R2 = (warp >> 1) * 16, C2 = (warp & 1) * 24;
    float acc2[3][4] = {};
    {
#pragma unroll
        for (int s = 0; s < 6; s++) {
            int r = R2 + g8;
            uint4 af0 = *(const uint4*)&sA[s * 1280 + r * 20 + m4 * 4];
            uint4 af1 = *(const uint4*)&sA[s * 1280 + (r + 8) * 20 + m4 * 4];
#pragma unroll
            for (int n = 0; n < 3; n++) {
                uint4 bf = ldw4(wsc, 96, C2 + n * 8 + g8, s, m4);
                MMA_TF32(acc2[n], af0.x, af1.x, af0.y, af1.y, bf.x, bf.y);
                MMA_TF32(acc2[n], af0.z, af1.z, af0.w, af1.w, bf.z, bf.w);
            }
        }
    }
    __syncthreads();

    {
        const int c0 = lane, c1 = lane + 32, c2 = lane + 64;
#pragma unroll 1
        for (int it = 0; it < 8; it++) {
            const int w = warp * 8 + it;
            float a0 = sb[c0], a1 = sb[c1], a2 = sb[c2];
#pragma unroll
            for (int ky = 0; ky < 3; ky++) {
                const float* rp = &srow[ky * 6144];
#pragma unroll
                for (int kx = 0; kx < 3; kx++) {
                    int ww = w + kx - 1;
                    if (ww < 0 || ww > 63) continue;
                    const float* p = rp + ww * 96;
                    int wi = ky * 3 + kx;
                    a0 = fmaf(p[c0], sw[c0 * 9 + wi], a0);
                    a1 = fmaf(p[c1], sw[c1 * 9 + wi], a1);
                    a2 = fmaf(p[c2], sw[c2 * 9 + wi], a2);
                }
            }
            float s = a0 + a1 + a2;
#pragma unroll
            for (int o = 16; o; o >>= 1) s += __shfl_xor_sync(0xffffffffu, s, o);
            float mu = s * (1.f / 96.f);
            float d0 = a0 - mu, d1 = a1 - mu, d2 = a2 - mu;
            float q = d0 * d0 + d1 * d1 + d2 * d2;
#pragma unroll
            for (int o = 16; o; o >>= 1) q += __shfl_xor_sync(0xffffffffu, q, o);
            float rs = rsqrtf(q * (1.f / 96.f) + 1e-6f);
            float z0 = d0 * rs * sg[c0] + sbe[c0];
            float z1 = d1 * rs * sg[c1] + sbe[c1];
            float z2 = d2 * rs * sg[c2] + sbe[c2];
            sA[(c0 >> 4) * 1280 + w * 20 + PERM(c0 & 15)] = f2tf(z0);
            sA[(c1 >> 4) * 1280 + w * 20 + PERM(c1 & 15)] = f2tf(z1);
            sA[(c2 >> 4) * 1280 + w * 20 + PERM(c2 & 15)] = f2tf(z2);
        }
    }
    __syncthreads();

#pragma unroll 1
    for (int half = 0; half < 2; half++) {
        {
            const int C = warp * 24;
            float acc[4][3][4] = {};
#pragma unroll
            for (int s = 0; s < 6; s++) {
                uint4 bf[3];
#pragma unroll
                for (int n = 0; n < 3; n++)
                    bf[n] = ldw4(w1, 96, half * 192 + C + n * 8 + g8, s, m4);
#pragma unroll
                for (int a = 0; a < 4; a++) {
                    int r = a * 16 + g8;
                    uint4 af0 = *(const uint4*)&sA[s * 1280 + r * 20 + m4 * 4];
                    uint4 af1 = *(const uint4*)&sA[s * 1280 + (r + 8) * 20 + m4 * 4];
#pragma unroll
                    for (int n = 0; n < 3; n++) {
                        MMA_TF32(acc[a][n], af0.x, af1.x, af0.y, af1.y, bf[n].x, bf[n].y);
                        MMA_TF32(acc[a][n], af0.z, af1.z, af0.w, af1.w, bf[n].z, bf[n].w);
                    }
                }
            }
#pragma unroll
            for (int a = 0; a < 4; a++) {
                int r = a * 16 + g8;
#pragma unroll
                for (int n = 0; n < 3; n++) {
                    int c = C + n * 8 + 2 * m4;
                    int cg = half * 192 + c;
                    float bb0 = pw1_b[cg], bb1 = pw1_b[cg + 1];
                    int s0 = (c >> 4) * 1280, p0 = PERM(c & 15);
                    int s1 = ((c + 1) >> 4) * 1280, p1 = PERM((c + 1) & 15);
                    sH[s0 + r * 20 + p0]       = f2tf(gelu_exact(acc[a][n][0] + bb0));
                    sH[s1 + r * 20 + p1]       = f2tf(gelu_exact(acc[a][n][1] + bb1));
                    sH[s0 + (r + 8) * 20 + p0] = f2tf(gelu_exact(acc[a][n][2] + bb0));
                    sH[s1 + (r + 8) * 20 + p1] = f2tf(gelu_exact(acc[a][n][3] + bb1));
                }
            }
        }
        __syncthreads();
        {
#pragma unroll
            for (int s = 0; s < 12; s++) {
                int r = R2 + g8;
                uint4 af0 = *(const uint4*)&sH[s * 1280 + r * 20 + m4 * 4];
                uint4 af1 = *(const uint4*)&sH[s * 1280 + (r + 8) * 20 + m4 * 4];
#pragma unroll
                for (int n = 0; n < 3; n++) {
                    uint4 bf = ldw4(w2, 384, C2 + n * 8 + g8, half * 12 + s, m4);
                    MMA_TF32(acc2[n], af0.x, af1.x, af0.y, af1.y, bf.x, bf.y);
                    MMA_TF32(acc2[n], af0.z, af1.z, af0.w, af1.w, bf.z, bf.w);
                }
            }
        }
        __syncthreads();
    }

    {
        int r = R2 + g8;
#pragma unroll
        for (int n = 0; n < 3; n++) {
            int c = C2 + n * 8 + 2 * m4;
            float bb0 = pw2_b[c] + sc_b[c], bb1 = pw2_b[c + 1] + sc_b[c + 1];
            sOut[r * 49 + c]           = acc2[n][0] + bb0;
            sOut[r * 49 + c + 1]       = acc2[n][1] + bb1;
            sOut[(r + 8) * 49 + c]     = acc2[n][2] + bb0;
            sOut[(r + 8) * 49 + c + 1] = acc2[n][3] + bb1;
        }
    }
    __syncthreads();
#pragma unroll
    for (int i = tid; i < 3072; i += 256) {
        int c = i >> 6, r = i & 63;
        out[((size_t)(n_img * 48 + c)) * 4096 + hw0 + r] = sOut[r * 49 + c];
    }
}

// ---------------- input transpose: x -> g_t AND g_cat lower half ----------------
__global__ void k_tin(const float* __restrict__ x) {
    __shared__ float sm[32][33];
    const int cf0 = blockIdx.x * 32, hw0 = blockIdx.y * 32, b = blockIdx.z;
    const int tx = threadIdx.x, ty = threadIdx.y;
#pragma unroll
    for (int yy = 0; yy < 4; yy++) {
        int cf = cf0 + ty + yy * 8;
        sm[ty + yy * 8][tx] = x[((size_t)b * 480 + cf) * 4096 + hw0 + tx];
    }
    __syncthreads();
    const int cf = cf0 + tx;
    const int s = cf / 48, f = cf - s * 48;
#pragma unroll
    for (int yy = 0; yy < 4; yy++) {
        int hw = hw0 + ty + yy * 8;
        float v = sm[tx][ty + yy * 8];
        g_t[((size_t)b * 4096 + hw) * 480 + cf] = v;
        g_cat[((size_t)(b * 10 + s) * 4096 + hw) * 96 + f] = v;
    }
}

// ---------------- host launcher ----------------
extern "C" void kernel_launch(void* const* d_in, const int* in_sizes, int n_in,
                              void* d_out, int out_size) {
    const float* x      = (const float*)d_in[0];
    const float* qkv_w  = (const float*)d_in[1];
    const float* qkv_b  = (const float*)d_in[2];
    const float* proj_w = (const float*)d_in[3];
    const float* proj_b = (const float*)d_in[4];
    const float* ff1_w  = (const float*)d_in[5];
    const float* ff1_b  = (const float*)d_in[6];
    const float* ff2_w  = (const float*)d_in[7];
    const float* ff2_b  = (const float*)d_in[8];
    const float* dw_w   = (const float*)d_in[9];
    const float* dw_b   = (const float*)d_in[10];
    const float* ln_g   = (const float*)d_in[11];
    const float* ln_b   = (const float*)d_in[12];
    const float* pw1_w  = (const float*)d_in[13];
    const float* pw1_b  = (const float*)d_in[14];
    const float* pw2_w  = (const float*)d_in[15];
    const float* pw2_b  = (const float*)d_in[16];
    const float* sc_w   = (const float*)d_in[17];
    const float* sc_b   = (const float*)d_in[18];
    float* out = (float*)d_out;

    static uint32_t* pw = nullptr;
    static bool init = false;
    if (!init) {
        cudaGetSymbolAddress((void**)&pw, g_wts);
        cudaFuncSetAttribute(f3_tail, cudaFuncAttributeMaxDynamicSharedMemorySize, 104448);
        init = true;
    }

    k_prep_all<<<450, 256>>>(qkv_w, proj_w, ff1_w, ff2_w, pw1_w, pw2_w, sc_w, pw);

    const dim3 tb32(32, 8);
    k_tin<<<dim3(15, 128, BB), tb32>>>(x);

    // layer 0
    f1_layer<<<4096, 192>>>(pw + OFF_QKV0, qkv_b, pw + OFF_PROJ0, proj_b);
    f2_ff<false><<<10240, 128>>>(pw + OFF_FF1_0, ff1_b, pw + OFF_FF2_0, ff2_b);
    // layer 1 (f2 writes straight into g_cat's upper 48 channels)
    f1_layer<<<4096, 192>>>(pw + OFF_QKV1, qkv_b + 144, pw + OFF_PROJ1, proj_b + 48);
    f2_ff<true><<<10240, 128>>>(pw + OFF_FF1_1, ff1_b + 192, pw + OFF_FF2_1, ff2_b + 48);

    f3_tail<<<5120, 256, 104448>>>(pw + OFF_PW1, pw1_b, pw + OFF_PW2, pw2_b,
                                   pw + OFF_SC, sc_b, dw_w, dw_b, ln_g, ln_b, out);
}

// round 17
// speedup vs baseline: 1.0092x; 1.0092x over previous
#include <cuda_runtime.h>
#include <cuda_fp16.h>
#include <math.h>
#include <stdint.h>

#define BB   8
#define TOK  327680

// ---------------- scratch ----------------
__device__ float g_t  [(size_t)TOK * 48];
__device__ float g_cat[(size_t)TOK * 96];
__device__ uint32_t g_wts[115200];   // pre-permuted tf32 weights

// weight offsets (words)
#define OFF_QKV0  0
#define OFF_QKV1  6912
#define OFF_PROJ0 13824
#define OFF_PROJ1 16128
#define OFF_FF1_0 18432
#define OFF_FF1_1 27648
#define OFF_FF2_0 36864
#define OFF_FF2_1 46080
#define OFF_PW1   55296
#define OFF_PW2   92160
#define OFF_SC    110592

__device__ __forceinline__ float gelu_exact(float v) {
    return 0.5f * v * (1.0f + erff(v * 0.70710678118654752f));
}
__device__ __forceinline__ uint32_t f2tf(float f) {
    uint32_t u;
    asm("cvt.rna.tf32.f32 %0, %1;" : "=r"(u) : "f"(f));
    return u;
}
__device__ __forceinline__ int PERM(int kk) { return 4 * (kk & 3) + (kk >> 2); }

#define MMA_TF32(c, a0, a1, a2, a3, b0, b1)                                 \
    asm volatile("mma.sync.aligned.m16n8k8.row.col.f32.tf32.tf32.f32 "     \
                 "{%0,%1,%2,%3}, {%4,%5,%6,%7}, {%8,%9}, {%0,%1,%2,%3};\n" \
                 : "+f"(c[0]), "+f"(c[1]), "+f"(c[2]), "+f"(c[3])          \
                 : "r"(a0), "r"(a1), "r"(a2), "r"(a3), "r"(b0), "r"(b1))

__device__ __forceinline__ uint4 ldw4(const uint32_t* __restrict__ Wt, int K,
                                      int c, int s, int m4) {
    return *(const uint4*)&Wt[(size_t)c * K + s * 16 + 4 * m4];
}

// ---------------- ONE fused weight prep kernel ----------------
__global__ void __launch_bounds__(256) k_prep_all(const float* __restrict__ qkv_w,
                                                  const float* __restrict__ proj_w,
                                                  const float* __restrict__ ff1_w,
                                                  const float* __restrict__ ff2_w,
                                                  const float* __restrict__ pw1_w,
                                                  const float* __restrict__ pw2_w,
                                                  const float* __restrict__ sc_w,
                                                  uint32_t* __restrict__ wt) {
    int b = blockIdx.x;
    if (b >= 432) {   // sc_w[o][c] (48x96): Wt[o][c-permuted]
        int i = (b - 432) * 256 + threadIdx.x;
        if (i < 48 * 96) {
            int o = i / 96, k = i % 96;
            int kk = k & 15;
            int pk = (k & ~15) + 4 * (kk & 3) + (kk >> 2);
            wt[OFF_SC + (size_t)o * 96 + pk] = f2tf(sc_w[i]);
        }
        return;
    }
    const float* W;
    uint32_t* Wt;
    int K, N, base;
    if (b < 27)       { W = qkv_w;          Wt = wt + OFF_QKV0;  K = 48;  N = 144; base = b; }
    else if (b < 54)  { W = qkv_w + 6912;   Wt = wt + OFF_QKV1;  K = 48;  N = 144; base = b - 27; }
    else if (b < 63)  { W = proj_w;         Wt = wt + OFF_PROJ0; K = 48;  N = 48;  base = b - 54; }
    else if (b < 72)  { W = proj_w + 2304;  Wt = wt + OFF_PROJ1; K = 48;  N = 48;  base = b - 63; }
    else if (b < 108) { W = ff1_w;          Wt = wt + OFF_FF1_0; K = 48;  N = 192; base = b - 72; }
    else if (b < 144) { W = ff1_w + 9216;   Wt = wt + OFF_FF1_1; K = 48;  N = 192; base = b - 108; }
    else if (b < 180) { W = ff2_w;          Wt = wt + OFF_FF2_0; K = 192; N = 48;  base = b - 144; }
    else if (b < 216) { W = ff2_w + 9216;   Wt = wt + OFF_FF2_1; K = 192; N = 48;  base = b - 180; }
    else if (b < 360) { W = pw1_w;          Wt = wt + OFF_PW1;   K = 96;  N = 384; base = b - 216; }
    else              { W = pw2_w;          Wt = wt + OFF_PW2;   K = 384; N = 48;  base = b - 360; }
    int i = base * 256 + threadIdx.x;
    if (i < K * N) {
        int k = i / N, c = i % N;
        int kk = k & 15;
        int pk = (k & ~15) + 4 * (kk & 3) + (kk >> 2);
        Wt[(size_t)c * K + pk] = f2tf(W[i]);
    }
}

// =====================================================================
// F1: fused qkv GEMM + banded attention + proj GEMM + residual
// =====================================================================
__global__ void __launch_bounds__(192, 3) f1_layer(const uint32_t* __restrict__ wq,
                                                   const float* __restrict__ qkv_b,
                                                   const uint32_t* __restrict__ wp,
                                                   const float* __restrict__ proj_b) {
    __shared__ uint32_t sAs[3 * 1600];
    __shared__ __half  sQKV[80 * 144];
    const int tid = threadIdx.x, lane = tid & 31, warp = tid >> 5;
    const int m4 = lane & 3, g8 = lane >> 2;
    const size_t row0 = (size_t)blockIdx.x * 80;

#pragma unroll
    for (int i = tid; i < 960; i += 192) {
        int row = i / 12, k0 = (i % 12) * 4;
        float4 v = *(const float4*)&g_t[(row0 + row) * 48 + k0];
        uint32_t* d = &sAs[(k0 >> 4) * 1600 + row * 20 + ((k0 & 15) >> 2)];
        d[0] = f2tf(v.x); d[4] = f2tf(v.y); d[8] = f2tf(v.z); d[12] = f2tf(v.w);
    }
    __syncthreads();

    {
        const int C = warp * 24;
        float acc[5][3][4] = {};
#pragma unroll
        for (int s = 0; s < 3; s++) {
            uint4 bf[3];
#pragma unroll
            for (int n = 0; n < 3; n++)
                bf[n] = ldw4(wq, 48, C + n * 8 + g8, s, m4);
#pragma unroll
            for (int a = 0; a < 5; a++) {
                int r = a * 16 + g8;
                uint4 af0 = *(const uint4*)&sAs[s * 1600 + r * 20 + m4 * 4];
                uint4 af1 = *(const uint4*)&sAs[s * 1600 + (r + 8) * 20 + m4 * 4];
#pragma unroll
                for (int n = 0; n < 3; n++) {
                    MMA_TF32(acc[a][n], af0.x, af1.x, af0.y, af1.y, bf[n].x, bf[n].y);
                    MMA_TF32(acc[a][n], af0.z, af1.z, af0.w, af1.w, bf[n].z, bf[n].w);
                }
            }
        }
#pragma unroll
        for (int a = 0; a < 5; a++) {
            int r = a * 16 + g8;
#pragma unroll
            for (int n = 0; n < 3; n++) {
                int c = C + n * 8 + 2 * m4;
                float b0 = qkv_b[c], b1 = qkv_b[c + 1];
                sQKV[r * 144 + c]           = __float2half(acc[a][n][0] + b0);
                sQKV[r * 144 + c + 1]       = __float2half(acc[a][n][1] + b1);
                sQKV[(r + 8) * 144 + c]     = __float2half(acc[a][n][2] + b0);
                sQKV[(r + 8) * 144 + c + 1] = __float2half(acc[a][n][3] + b1);
            }
        }
    }
    __syncthreads();

    {
        const int pair = tid & 63, chunk = tid >> 6;
        const int sl = pair >> 3, hh = pair & 7;
        const int ibeg = (chunk == 0) ? 0 : (chunk == 1) ? 4 : 7;
        const int iend = (chunk == 0) ? 4 : (chunk == 1) ? 7 : 10;
        const __half* base = sQKV + sl * 1440;
        const float scale = 0.40824829046386301637f;
        for (int i = ibeg; i < iend; i++) {
            const __half* ki = base + i * 144 + 48 + hh * 6;
            int jlo = (i > 0) ? i - 1 : 0;
            int jhi = (i < 9) ? i + 1 : 9;
            float lg[3];
            float mx = -1e30f;
            for (int j = jlo; j <= jhi; j++) {
                const __half* qj = base + j * 144 + hh * 6;
                float d = 0.f;
#pragma unroll
                for (int dd = 0; dd < 6; dd++)
                    d += __half2float(ki[dd]) * __half2float(qj[dd]);
                d *= scale;
                lg[j - jlo] = d;
                mx = fmaxf(mx, d);
            }
            float se = 0.f;
            for (int j = jlo; j <= jhi; j++) {
                lg[j - jlo] = expf(lg[j - jlo] - mx);
                se += lg[j - jlo];
            }
            float inv = 1.f / se;
            int row = sl * 10 + i;
#pragma unroll
            for (int dd = 0; dd < 6; dd++) {
                float o = 0.f;
                for (int j = jlo; j <= jhi; j++)
                    o += lg[j - jlo] * __half2float(base[j * 144 + 96 + hh * 6 + dd]);
                o *= inv;
                int col = hh * 6 + dd;
                sAs[(col >> 4) * 1600 + row * 20 + PERM(col & 15)] = f2tf(o);
            }
        }
    }
    __syncthreads();

    {
        const int C = warp * 8;
        float acc[5][4] = {};
#pragma unroll
        for (int s = 0; s < 3; s++) {
            uint4 bf = ldw4(wp, 48, C + g8, s, m4);
#pragma unroll
            for (int a = 0; a < 5; a++) {
                int r = a * 16 + g8;
                uint4 af0 = *(const uint4*)&sAs[s * 1600 + r * 20 + m4 * 4];
                uint4 af1 = *(const uint4*)&sAs[s * 1600 + (r + 8) * 20 + m4 * 4];
                MMA_TF32(acc[a], af0.x, af1.x, af0.y, af1.y, bf.x, bf.y);
                MMA_TF32(acc[a], af0.z, af1.z, af0.w, af1.w, bf.z, bf.w);
            }
        }
        const int c = C + 2 * m4;
        const float b0 = proj_b[c], b1 = proj_b[c + 1];
#pragma unroll
        for (int a = 0; a < 5; a++) {
            int r = a * 16 + g8;
            float2 t0 = *(const float2*)&g_t[(row0 + r) * 48 + c];
            float2 t1 = *(const float2*)&g_t[(row0 + r + 8) * 48 + c];
            *(float2*)&g_t[(row0 + r) * 48 + c] =
                make_float2(acc[a][0] + b0 + t0.x, acc[a][1] + b1 + t0.y);
            *(float2*)&g_t[(row0 + r + 8) * 48 + c] =
                make_float2(acc[a][2] + b0 + t1.x, acc[a][3] + b1 + t1.y);
        }
    }
}

// =====================================================================
// F2: fused ff1+GELU -> ff2 + residual (R16 form)
// =====================================================================
template<bool CAT>
__global__ void __launch_bounds__(128, 6) f2_ff(const uint32_t* __restrict__ w1,
                                                const float* __restrict__ b1,
                                                const uint32_t* __restrict__ w2,
                                                const float* __restrict__ b2) {
    __shared__ uint32_t sA[3 * 640];
    __shared__ uint32_t sH[6 * 640];
    const int tid = threadIdx.x, lane = tid & 31, warp = tid >> 5;
    const int m4 = lane & 3, g8 = lane >> 2;
    const size_t row0 = (size_t)blockIdx.x * 32;

#pragma unroll
    for (int i = tid; i < 384; i += 128) {
        int row = i / 12, k0 = (i % 12) * 4;
        float4 v = *(const float4*)&g_t[(row0 + row) * 48 + k0];
        uint32_t* d = &sA[(k0 >> 4) * 640 + row * 20 + ((k0 & 15) >> 2)];
        d[0] = f2tf(v.x); d[4] = f2tf(v.y); d[8] = f2tf(v.z); d[12] = f2tf(v.w);
    }
    __syncthreads();

    const int R2 = (warp >> 1) * 16, C2 = (warp & 1) * 24;
    float acc2[3][4] = {};

#pragma unroll 1
    for (int half = 0; half < 2; half++) {
        {
            const int Cg = half * 96 + warp * 24;
            float acc[2][3][4] = {};
#pragma unroll
            for (int s = 0; s < 3; s++) {
                uint4 af[2][2];
#pragma unroll
                for (int m = 0; m < 2; m++) {
                    int r = m * 16 + g8;
                    af[m][0] = *(const uint4*)&sA[s * 640 + r * 20 + m4 * 4];
                    af[m][1] = *(const uint4*)&sA[s * 640 + (r + 8) * 20 + m4 * 4];
                }
                uint4 bf[3];
#pragma unroll
                for (int n = 0; n < 3; n++)
                    bf[n] = ldw4(w1, 48, Cg + n * 8 + g8, s, m4);
#pragma unroll
                for (int m = 0; m < 2; m++)
#pragma unroll
                    for (int n = 0; n < 3; n++) {
                        MMA_TF32(acc[m][n], af[m][0].x, af[m][1].x, af[m][0].y, af[m][1].y, bf[n].x, bf[n].y);
                        MMA_TF32(acc[m][n], af[m][0].z, af[m][1].z, af[m][0].w, af[m][1].w, bf[n].z, bf[n].w);
                    }
            }
#pragma unroll
            for (int m = 0; m < 2; m++) {
                int r = m * 16 + g8;
#pragma unroll
                for (int n = 0; n < 3; n++) {
                    int cl = warp * 24 + n * 8 + 2 * m4;
                    int cg = half * 96 + cl;
                    float bb0 = b1[cg], bb1 = b1[cg + 1];
                    int s0 = (cl >> 4) * 640, p0 = PERM(cl & 15);
                    int s1 = ((cl + 1) >> 4) * 640, p1 = PERM((cl + 1) & 15);
                    sH[s0 + r * 20 + p0]       = f2tf(gelu_exact(acc[m][n][0] + bb0));
                    sH[s1 + r * 20 + p1]       = f2tf(gelu_exact(acc[m][n][1] + bb1));
                    sH[s0 + (r + 8) * 20 + p0] = f2tf(gelu_exact(acc[m][n][2] + bb0));
                    sH[s1 + (r + 8) * 20 + p1] = f2tf(gelu_exact(acc[m][n][3] + bb1));
                }
            }
        }
        __syncthreads();
        {
#pragma unroll
            for (int s = 0; s < 6; s++) {
                int r = R2 + g8;
                uint4 af0 = *(const uint4*)&sH[s * 640 + r * 20 + m4 * 4];
                uint4 af1 = *(const uint4*)&sH[s * 640 + (r + 8) * 20 + m4 * 4];
#pragma unroll
                for (int n = 0; n < 3; n++) {
                    uint4 bf = ldw4(w2, 192, C2 + n * 8 + g8, half * 6 + s, m4);
                    MMA_TF32(acc2[n], af0.x, af1.x, af0.y, af1.y, bf.x, bf.y);
                    MMA_TF32(acc2[n], af0.z, af1.z, af0.w, af1.w, bf.z, bf.w);
                }
            }
        }
        __syncthreads();
    }

    {
        const int r = R2 + g8;
        const size_t rowA = row0 + r, rowB = row0 + r + 8;
        size_t pixA = 0, pixB = 0;
        if (CAT) {
            int bA = (int)(rowA / 40960), remA = (int)(rowA % 40960);
            int bB = (int)(rowB / 40960), remB = (int)(rowB % 40960);
            pixA = ((size_t)(bA * 10 + remA % 10) * 4096 + remA / 10) * 96 + 48;
            pixB = ((size_t)(bB * 10 + remB % 10) * 4096 + remB / 10) * 96 + 48;
        }
#pragma unroll
        for (int n = 0; n < 3; n++) {
            int c = C2 + n * 8 + 2 * m4;
            float bb0 = b2[c], bb1 = b2[c + 1];
            float2 t0 = *(const float2*)&g_t[rowA * 48 + c];
            float2 t1 = *(const float2*)&g_t[rowB * 48 + c];
            float2 v0 = make_float2(acc2[n][0] + bb0 + t0.x, acc2[n][1] + bb1 + t0.y);
            float2 v1 = make_float2(acc2[n][2] + bb0 + t1.x, acc2[n][3] + bb1 + t1.y);
            if (CAT) {
                *(float2*)&g_cat[pixA + c] = v0;
                *(float2*)&g_cat[pixB + c] = v1;
            } else {
                *(float2*)&g_t[rowA * 48 + c] = v0;
                *(float2*)&g_t[rowB * 48 + c] = v1;
            }
        }
    }
}

// =====================================================================
// F3v3: dwconv+LN (direct global halo reads) + sc GEMM + pw1/pw2 in
// 4 quarters of 96 cols. smem ~61KB dyn -> 3 blocks/SM, 24 warps.
// =====================================================================
__global__ void __launch_bounds__(256, 3) f3_tail(const uint32_t* __restrict__ w1,
                                                  const float* __restrict__ pw1_b,
                                                  const uint32_t* __restrict__ w2,
                                                  const float* __restrict__ pw2_b,
                                                  const uint32_t* __restrict__ wsc,
                                                  const float* __restrict__ sc_b,
                                                  const float* __restrict__ wdw,
                                                  const float* __restrict__ bdw,
                                                  const float* __restrict__ gam,
                                                  const float* __restrict__ bet,
                                                  float* __restrict__ out) {
    extern __shared__ uint32_t dyn[];
    uint32_t* sA = dyn;                    // 7680 words: cat tile, then z tile
    uint32_t* sH = dyn + 7680;             // 7680 words: hidden quarter
    float* sOut  = (float*)(dyn + 7680);   // 3136 floats (aliases sH at end)
    __shared__ float sw[864], sb[96], sg[96], sbe[96];

    const int tid = threadIdx.x, lane = tid & 31, warp = tid >> 5;
    const int m4 = lane & 3, g8 = lane >> 2;
    const int n_img = blockIdx.x >> 6, h = blockIdx.x & 63;
    const int hw0 = h * 64;
    const size_t pixbase = (size_t)n_img * 4096 + hw0;

    for (int i = tid; i < 864; i += 256) sw[i] = wdw[i];
    if (tid < 96) {
        sb[tid] = bdw[tid];
        sg[tid] = gam[tid];
        sbe[tid] = bet[tid];
    }

    // ---- 1. cat middle row -> sA permuted ----
#pragma unroll
    for (int i = tid; i < 1536; i += 256) {
        int row = i / 24, k0 = (i % 24) * 4;
        float4 v = *(const float4*)&g_cat[(pixbase + row) * 96 + k0];
        uint32_t* d = &sA[(k0 >> 4) * 1280 + row * 20 + ((k0 & 15) >> 2)];
        d[0] = f2tf(v.x); d[4] = f2tf(v.y); d[8] = f2tf(v.z); d[12] = f2tf(v.w);
    }
    __syncthreads();

    // ---- 2. sc GEMM (64x48, K=96) -> acc2 ----
    const int R2 = (warp >> 1) * 16, C2 = (warp & 1) * 24;
    float acc2[3][4] = {};
#pragma unroll
    for (int s = 0; s < 6; s++) {
        int r = R2 + g8;
        uint4 af0 = *(const uint4*)&sA[s * 1280 + r * 20 + m4 * 4];
        uint4 af1 = *(const uint4*)&sA[s * 1280 + (r + 8) * 20 + m4 * 4];
#pragma unroll
        for (int n = 0; n < 3; n++) {
            uint4 bf = ldw4(wsc, 96, C2 + n * 8 + g8, s, m4);
            MMA_TF32(acc2[n], af0.x, af1.x, af0.y, af1.y, bf.x, bf.y);
            MMA_TF32(acc2[n], af0.z, af1.z, af0.w, af1.w, bf.z, bf.w);
        }
    }
    __syncthreads();

    // ---- 3. dwconv + LN with direct global halo reads -> sA permuted ----
    {
        const int c0 = lane, c1 = lane + 32, c2 = lane + 64;
#pragma unroll 1
        for (int it = 0; it < 8; it++) {
            const int w = warp * 8 + it;
            float a0 = sb[c0], a1 = sb[c1], a2 = sb[c2];
#pragma unroll
            for (int ky = 0; ky < 3; ky++) {
                int hh = h + ky - 1;
                if (hh < 0 || hh > 63) continue;
#pragma unroll
                for (int kx = 0; kx < 3; kx++) {
                    int ww = w + kx - 1;
                    if (ww < 0 || ww > 63) continue;
                    const float* p = &g_cat[((size_t)n_img * 4096 + hh * 64 + ww) * 96];
                    int wi = ky * 3 + kx;
                    a0 = fmaf(p[c0], sw[c0 * 9 + wi], a0);
                    a1 = fmaf(p[c1], sw[c1 * 9 + wi], a1);
                    a2 = fmaf(p[c2], sw[c2 * 9 + wi], a2);
                }
            }
            float s = a0 + a1 + a2;
#pragma unroll
            for (int o = 16; o; o >>= 1) s += __shfl_xor_sync(0xffffffffu, s, o);
            float mu = s * (1.f / 96.f);
            float d0 = a0 - mu, d1 = a1 - mu, d2 = a2 - mu;
            float q = d0 * d0 + d1 * d1 + d2 * d2;
#pragma unroll
            for (int o = 16; o; o >>= 1) q += __shfl_xor_sync(0xffffffffu, q, o);
            float rs = rsqrtf(q * (1.f / 96.f) + 1e-6f);
            float z0 = d0 * rs * sg[c0] + sbe[c0];
            float z1 = d1 * rs * sg[c1] + sbe[c1];
            float z2 = d2 * rs * sg[c2] + sbe[c2];
            sA[(c0 >> 4) * 1280 + w * 20 + PERM(c0 & 15)] = f2tf(z0);
            sA[(c1 >> 4) * 1280 + w * 20 + PERM(c1 & 15)] = f2tf(z1);
            sA[(c2 >> 4) * 1280 + w * 20 + PERM(c2 & 15)] = f2tf(z2);
        }
    }
    __syncthreads();

    // ---- 4. pw1+GELU -> sH, pw2 accumulate, in 4 quarters of 96 cols ----
#pragma unroll 1
    for (int q = 0; q < 4; q++) {
        {
            const int Rm = (warp >> 2) * 32;      // 0 or 32
            const int Cl = (warp & 3) * 24;       // local col in quarter
            float acc[2][3][4] = {};
#pragma unroll
            for (int s = 0; s < 6; s++) {
                uint4 bf[3];
#pragma unroll
                for (int n = 0; n < 3; n++)
                    bf[n] = ldw4(w1, 96, q * 96 + Cl + n * 8 + g8, s, m4);
#pragma unroll
                for (int a = 0; a < 2; a++) {
                    int r = Rm + a * 16 + g8;
                    uint4 af0 = *(const uint4*)&sA[s * 1280 + r * 20 + m4 * 4];
                    uint4 af1 = *(const uint4*)&sA[s * 1280 + (r + 8) * 20 + m4 * 4];
#pragma unroll
                    for (int n = 0; n < 3; n++) {
                        MMA_TF32(acc[a][n], af0.x, af1.x, af0.y, af1.y, bf[n].x, bf[n].y);
                        MMA_TF32(acc[a][n], af0.z, af1.z, af0.w, af1.w, bf[n].z, bf[n].w);
                    }
                }
            }
#pragma unroll
            for (int a = 0; a < 2; a++) {
                int r = Rm + a * 16 + g8;
#pragma unroll
                for (int n = 0; n < 3; n++) {
                    int cl = Cl + n * 8 + 2 * m4;       // local col in quarter
                    int cg = q * 96 + cl;
                    float bb0 = pw1_b[cg], bb1 = pw1_b[cg + 1];
                    int s0 = (cl >> 4) * 1280, p0 = PERM(cl & 15);
                    int s1 = ((cl + 1) >> 4) * 1280, p1 = PERM((cl + 1) & 15);
                    sH[s0 + r * 20 + p0]       = f2tf(gelu_exact(acc[a][n][0] + bb0));
                    sH[s1 + r * 20 + p1]       = f2tf(gelu_exact(acc[a][n][1] + bb1));
                    sH[s0 + (r + 8) * 20 + p0] = f2tf(gelu_exact(acc[a][n][2] + bb0));
                    sH[s1 + (r + 8) * 20 + p1] = f2tf(gelu_exact(acc[a][n][3] + bb1));
                }
            }
        }
        __syncthreads();
        {
#pragma unroll
            for (int s = 0; s < 6; s++) {
                int r = R2 + g8;
                uint4 af0 = *(const uint4*)&sH[s * 1280 + r * 20 + m4 * 4];
                uint4 af1 = *(const uint4*)&sH[s * 1280 + (r + 8) * 20 + m4 * 4];
#pragma unroll
                for (int n = 0; n < 3; n++) {
                    uint4 bf = ldw4(w2, 384, C2 + n * 8 + g8, q * 6 + s, m4);
                    MMA_TF32(acc2[n], af0.x, af1.x, af0.y, af1.y, bf.x, bf.y);
                    MMA_TF32(acc2[n], af0.z, af1.z, af0.w, af1.w, bf.z, bf.w);
                }
            }
        }
        __syncthreads();
    }

    // ---- 5. epilogue: stage into sOut (aliases sH), transposed store ----
    {
        int r = R2 + g8;
#pragma unroll
        for (int n = 0; n < 3; n++) {
            int c = C2 + n * 8 + 2 * m4;
            float bb0 = pw2_b[c] + sc_b[c], bb1 = pw2_b[c + 1] + sc_b[c + 1];
            sOut[r * 49 + c]           = acc2[n][0] + bb0;
            sOut[r * 49 + c + 1]       = acc2[n][1] + bb1;
            sOut[(r + 8) * 49 + c]     = acc2[n][2] + bb0;
            sOut[(r + 8) * 49 + c + 1] = acc2[n][3] + bb1;
        }
    }
    __syncthreads();
#pragma unroll
    for (int i = tid; i < 3072; i += 256) {
        int c = i >> 6, r = i & 63;
        out[((size_t)(n_img * 48 + c)) * 4096 + hw0 + r] = sOut[r * 49 + c];
    }
}

// ---------------- input transpose: x -> g_t AND g_cat lower half ----------------
__global__ void k_tin(const float* __restrict__ x) {
    __shared__ float sm[32][33];
    const int cf0 = blockIdx.x * 32, hw0 = blockIdx.y * 32, b = blockIdx.z;
    const int tx = threadIdx.x, ty = threadIdx.y;
#pragma unroll
    for (int yy = 0; yy < 4; yy++) {
        int cf = cf0 + ty + yy * 8;
        sm[ty + yy * 8][tx] = x[((size_t)b * 480 + cf) * 4096 + hw0 + tx];
    }
    __syncthreads();
    const int cf = cf0 + tx;
    const int s = cf / 48, f = cf - s * 48;
#pragma unroll
    for (int yy = 0; yy < 4; yy++) {
        int hw = hw0 + ty + yy * 8;
        float v = sm[tx][ty + yy * 8];
        g_t[((size_t)b * 4096 + hw) * 480 + cf] = v;
        g_cat[((size_t)(b * 10 + s) * 4096 + hw) * 96 + f] = v;
    }
}

// ---------------- host launcher ----------------
extern "C" void kernel_launch(void* const* d_in, const int* in_sizes, int n_in,
                              void* d_out, int out_size) {
    const float* x      = (const float*)d_in[0];
    const float* qkv_w  = (const float*)d_in[1];
    const float* qkv_b  = (const float*)d_in[2];
    const float* proj_w = (const float*)d_in[3];
    const float* proj_b = (const float*)d_in[4];
    const float* ff1_w  = (const float*)d_in[5];
    const float* ff1_b  = (const float*)d_in[6];
    const float* ff2_w  = (const float*)d_in[7];
    const float* ff2_b  = (const float*)d_in[8];
    const float* dw_w   = (const float*)d_in[9];
    const float* dw_b   = (const float*)d_in[10];
    const float* ln_g   = (const float*)d_in[11];
    const float* ln_b   = (const float*)d_in[12];
    const float* pw1_w  = (const float*)d_in[13];
    const float* pw1_b  = (const float*)d_in[14];
    const float* pw2_w  = (const float*)d_in[15];
    const float* pw2_b  = (const float*)d_in[16];
    const float* sc_w   = (const float*)d_in[17];
    const float* sc_b   = (const float*)d_in[18];
    float* out = (float*)d_out;

    static uint32_t* pw = nullptr;
    static bool init = false;
    if (!init) {
        cudaGetSymbolAddress((void**)&pw, g_wts);
        cudaFuncSetAttribute(f3_tail, cudaFuncAttributeMaxDynamicSharedMemorySize, 61440);
        init = true;
    }

    k_prep_all<<<450, 256>>>(qkv_w, proj_w, ff1_w, ff2_w, pw1_w, pw2_w, sc_w, pw);

    const dim3 tb32(32, 8);
    k_tin<<<dim3(15, 128, BB), tb32>>>(x);

    // layer 0
    f1_layer<<<4096, 192>>>(pw + OFF_QKV0, qkv_b, pw + OFF_PROJ0, proj_b);
    f2_ff<false><<<10240, 128>>>(pw + OFF_FF1_0, ff1_b, pw + OFF_FF2_0, ff2_b);
    // layer 1 (f2 writes straight into g_cat's upper 48 channels)
    f1_layer<<<4096, 192>>>(pw + OFF_QKV1, qkv_b + 144, pw + OFF_PROJ1, proj_b + 48);
    f2_ff<true><<<10240, 128>>>(pw + OFF_FF1_1, ff1_b + 192, pw + OFF_FF2_1, ff2_b + 48);

    f3_tail<<<5120, 256, 61440>>>(pw + OFF_PW1, pw1_b, pw + OFF_PW2, pw2_b,
                                  pw + OFF_SC, sc_b, dw_w, dw_b, ln_g, ln_b, out);
}